// round 7
// baseline (speedup 1.0000x reference)
#include <cuda_runtime.h>
#include <math.h>
#include <stdint.h>

#define BB   32
#define MM   16384
#define WW   256
#define HH   16
#define EPS  1e-5f

#define MT      256
#define THREADS 256
#define NCHK    16            // 16-col k chunks
#define DEPTH   3             // cp.async stages per warp

// smem byte layout
#define SM_A     0            // 8 warps x 3 stages x 2048B = 49152
#define SM_BH    49152        // 16 chunks x 4 tiles x 128B = 8192
#define SM_BL    57344        // 8192
#define SM_KN    65536        // 16 f32
#define SM_SP    65600        // 16 f32
#define SM_TOTAL 65664
// sharp staging overlays SM_A after the main loop (16 x 264 f32 = 16896B)
#define SHARP_PITCH 264

__device__ __forceinline__ unsigned pack2(float hi_el, float lo_el) {
    unsigned r;
    asm("cvt.rn.satfinite.bf16x2.f32 %0, %1, %2;" : "=r"(r) : "f"(hi_el), "f"(lo_el));
    return r;
}
__device__ __forceinline__ void ldsm4(unsigned addr, unsigned& r0, unsigned& r1,
                                      unsigned& r2, unsigned& r3) {
    asm volatile("ldmatrix.sync.aligned.m8n8.x4.shared.b16 {%0,%1,%2,%3}, [%4];"
                 : "=r"(r0), "=r"(r1), "=r"(r2), "=r"(r3) : "r"(addr));
}
__device__ __forceinline__ void mma16816(float* d, unsigned a0, unsigned a1,
                                         unsigned a2, unsigned a3,
                                         unsigned b0, unsigned b1) {
    asm volatile(
        "mma.sync.aligned.m16n8k16.row.col.f32.bf16.bf16.f32 "
        "{%0,%1,%2,%3}, {%4,%5,%6,%7}, {%8,%9}, {%0,%1,%2,%3};"
        : "+f"(d[0]), "+f"(d[1]), "+f"(d[2]), "+f"(d[3])
        : "r"(a0), "r"(a1), "r"(a2), "r"(a3), "r"(b0), "r"(b1));
}
__device__ __forceinline__ void cp_async16(unsigned smem_addr, const void* gptr) {
    asm volatile("cp.async.cg.shared.global [%0], [%1], 16;"
                 :: "r"(smem_addr), "l"(gptr));
}
__device__ __forceinline__ void cp_commit() {
    asm volatile("cp.async.commit_group;");
}
__device__ __forceinline__ void cp_wait2() {
    asm volatile("cp.async.wait_group 2;");
}
__device__ __forceinline__ float4 lds128(unsigned addr) {
    float4 v;
    asm volatile("ld.shared.v4.f32 {%0,%1,%2,%3}, [%4];"
                 : "=f"(v.x), "=f"(v.y), "=f"(v.z), "=f"(v.w) : "r"(addr));
    return v;
}
__device__ __forceinline__ float softplus_f(float x) {
    return fmaxf(x, 0.0f) + log1pf(__expf(-fabsf(x)));
}
// split float4 into hi/lo bf16x2 pairs: p01=(x,y), p23=(z,w)
__device__ __forceinline__ void split4(float4 v, unsigned& h01, unsigned& h23,
                                       unsigned& l01, unsigned& l23) {
    h01 = pack2(v.y, v.x);
    h23 = pack2(v.w, v.z);
    float ax = __uint_as_float(h01 << 16);
    float ay = __uint_as_float(h01 & 0xffff0000u);
    float az = __uint_as_float(h23 << 16);
    float aw = __uint_as_float(h23 & 0xffff0000u);
    l01 = pack2(v.y - ay, v.x - ax);
    l23 = pack2(v.w - aw, v.z - az);
}

__global__ void __launch_bounds__(THREADS, 3)
pass1_kernel(const float* __restrict__ memory,
             const float* __restrict__ keys,
             const float* __restrict__ strengths,
             float* __restrict__ out) {
    extern __shared__ char sm[];
    float* smf = (float*)sm;
    unsigned sb;
    asm("{ .reg .u64 t; cvta.to.shared.u64 t, %1; cvt.u32.u64 %0, t; }"
        : "=r"(sb) : "l"(sm));

    const int tid  = threadIdx.x;
    const int lane = tid & 31;
    const int wid  = tid >> 5;
    const int b    = blockIdx.y;
    const int m0   = blockIdx.x * MT;

    const int r = lane >> 2;          // fragment row 0..7
    const int c = lane & 3;           // fragment col group

    // A source: rows (wid*32 + r) + {0,8,16,24}, cols chunk*16 + 4c
    const float* ap = memory + ((size_t)b * MM + m0 + wid * 32 + r) * WW + 4 * c;
    // per-warp smem ring; each lane copies/reads its own 16B
    const unsigned aring = sb + SM_A + wid * (DEPTH * 2048) + lane * 16;

    // ---- prologue: issue stages 0..1 ----
    #pragma unroll
    for (int s = 0; s < DEPTH - 1; s++) {
        #pragma unroll
        for (int j = 0; j < 4; j++)
            cp_async16(aring + s * 2048 + j * 512, ap + (size_t)j * 8 * WW + s * 16);
        cp_commit();
    }

    // ---- keys: permuted bf16 hi/lo B tiles + norms + softplus ----
    {
        const int h = tid >> 4;       // 0..15
        const int t = tid & 15;       // chunk
        const float* kp = keys + (size_t)b * HH * WW + h * WW + t * 16;
        float4 kv[4];
        #pragma unroll
        for (int j = 0; j < 4; j++) kv[j] = *(const float4*)(kp + 4 * j);

        float ss = 0.0f;
        #pragma unroll
        for (int j = 0; j < 4; j++) {
            ss = fmaf(kv[j].x, kv[j].x, ss); ss = fmaf(kv[j].y, kv[j].y, ss);
            ss = fmaf(kv[j].z, kv[j].z, ss); ss = fmaf(kv[j].w, kv[j].w, ss);
        }
        ss += __shfl_xor_sync(0xffffffffu, ss, 1);
        ss += __shfl_xor_sync(0xffffffffu, ss, 2);
        ss += __shfl_xor_sync(0xffffffffu, ss, 4);
        ss += __shfl_xor_sync(0xffffffffu, ss, 8);
        if (t == 0) {
            smf[SM_KN / 4 + h] = sqrtf(ss + EPS);
            smf[SM_SP / 4 + h] = softplus_f(strengths[b * HH + h]);
        }

        // tiles per chunk: [0]=(h0-7,k0-7) [1]=(h8-15,k0-7) [2]=(h0-7,k8-15) [3]=(h8-15,k8-15)
        unsigned base = (unsigned)(t * 512 + (h >> 3) * 128 + (h & 7) * 16);
        #pragma unroll
        for (int q = 0; q < 4; q++) {   // actual col quad
            unsigned h01, h23, l01, l23;
            split4(kv[q], h01, h23, l01, l23);
            *(unsigned*)(sm + SM_BH + base + q * 4)       = h01;
            *(unsigned*)(sm + SM_BH + base + 256 + q * 4) = h23;
            *(unsigned*)(sm + SM_BL + base + q * 4)       = l01;
            *(unsigned*)(sm + SM_BL + base + 256 + q * 4) = l23;
        }
    }
    __syncthreads();

    // ---- main loop: per-warp cp.async pipeline, no barriers ----
    float d[2][2][4];
    #pragma unroll
    for (int mt = 0; mt < 2; mt++)
        #pragma unroll
        for (int nt = 0; nt < 2; nt++)
            #pragma unroll
            for (int i = 0; i < 4; i++) d[mt][nt][i] = 0.0f;

    float ss4[4] = {0.0f, 0.0f, 0.0f, 0.0f};

    const unsigned bl_off = (unsigned)((lane >> 3) * 128 + (lane & 7) * 16);

    #pragma unroll
    for (int t = 0; t < NCHK; t++) {
        // issue chunk t+2 (or empty commit to keep group count uniform)
        if (t + DEPTH - 1 < NCHK) {
            unsigned dst = aring + ((t + DEPTH - 1) % DEPTH) * 2048;
            #pragma unroll
            for (int j = 0; j < 4; j++)
                cp_async16(dst + j * 512,
                           ap + (size_t)j * 8 * WW + (t + DEPTH - 1) * 16);
        }
        cp_commit();
        cp_wait2();            // chunk t's group complete

        // B fragments
        unsigned bh[4], bl[4];
        ldsm4(sb + SM_BH + bl_off + t * 512, bh[0], bh[1], bh[2], bh[3]);
        ldsm4(sb + SM_BL + bl_off + t * 512, bl[0], bl[1], bl[2], bl[3]);

        // A from own ring slot + convert + norms
        const unsigned src = aring + (t % DEPTH) * 2048;
        unsigned ah01[4], ah23[4], al01[4], al23[4];
        #pragma unroll
        for (int j = 0; j < 4; j++) {
            float4 w = lds128(src + j * 512);
            ss4[j] = fmaf(w.x, w.x, ss4[j]);
            ss4[j] = fmaf(w.y, w.y, ss4[j]);
            ss4[j] = fmaf(w.z, w.z, ss4[j]);
            ss4[j] = fmaf(w.w, w.w, ss4[j]);
            split4(w, ah01[j], ah23[j], al01[j], al23[j]);
        }

        // tile0 = rows (v0, v1), tile1 = rows (v2, v3)
        #pragma unroll
        for (int mt = 0; mt < 2; mt++) {
            int j0 = mt * 2, j1 = mt * 2 + 1;
            mma16816(d[mt][0], ah01[j0], ah01[j1], ah23[j0], ah23[j1], bh[0], bh[2]);
            mma16816(d[mt][0], ah01[j0], ah01[j1], ah23[j0], ah23[j1], bl[0], bl[2]);
            mma16816(d[mt][0], al01[j0], al01[j1], al23[j0], al23[j1], bh[0], bh[2]);
            mma16816(d[mt][1], ah01[j0], ah01[j1], ah23[j0], ah23[j1], bh[1], bh[3]);
            mma16816(d[mt][1], ah01[j0], ah01[j1], ah23[j0], ah23[j1], bl[1], bl[3]);
            mma16816(d[mt][1], al01[j0], al01[j1], al23[j0], al23[j1], bh[1], bh[3]);
        }
    }

    // ---- row norms: reduce across the 4-lane col group ----
    #pragma unroll
    for (int j = 0; j < 4; j++) {
        ss4[j] += __shfl_xor_sync(0xffffffffu, ss4[j], 1);
        ss4[j] += __shfl_xor_sync(0xffffffffu, ss4[j], 2);
        ss4[j] = sqrtf(ss4[j] + EPS);    // mem norm of row (wid*32 + 16*(j>>1) + r + 8*(j&1))
    }

    __syncthreads();   // all warps done with A ring before sharp overlays it

    // ---- sharpen into smem staging (overlays A ring) ----
    {
        float* sharp = smf;   // [16][SHARP_PITCH]
        #pragma unroll
        for (int nt = 0; nt < 2; nt++) {
            int h0 = nt * 8 + 2 * c;
            float sp0 = smf[SM_SP / 4 + h0],     kn0 = smf[SM_KN / 4 + h0];
            float sp1 = smf[SM_SP / 4 + h0 + 1], kn1 = smf[SM_KN / 4 + h0 + 1];
            #pragma unroll
            for (int mt = 0; mt < 2; mt++) {
                int row_lo = wid * 32 + 16 * mt + r;
                float mn_lo = ss4[2 * mt];
                float mn_hi = ss4[2 * mt + 1];
                sharp[h0 * SHARP_PITCH + row_lo] =
                    __fdividef(d[mt][nt][0] * sp0, fmaf(kn0, mn_lo, EPS));
                sharp[(h0 + 1) * SHARP_PITCH + row_lo] =
                    __fdividef(d[mt][nt][1] * sp1, fmaf(kn1, mn_lo, EPS));
                sharp[h0 * SHARP_PITCH + row_lo + 8] =
                    __fdividef(d[mt][nt][2] * sp0, fmaf(kn0, mn_hi, EPS));
                sharp[(h0 + 1) * SHARP_PITCH + row_lo + 8] =
                    __fdividef(d[mt][nt][3] * sp1, fmaf(kn1, mn_hi, EPS));
            }
        }
    }
    __syncthreads();

    // ---- coalesced write ----
    {
        const float* sharp = smf;
        float4* o4 = (float4*)out;
        #pragma unroll
        for (int u = 0; u < 4; u++) {
            int f  = tid + 256 * u;     // 1024 float4
            int h  = f >> 6;
            int r4 = f & 63;
            float4 w = *(const float4*)(sharp + h * SHARP_PITCH + r4 * 4);
            o4[(((size_t)b * HH + h) * MM + m0) / 4 + r4] = w;
        }
    }
}

// ---- pass 2: in-place softmax over M per (b,h) row ----
// No max-subtraction: sharp = cos_sim * softplus(strength) is bounded (|x| < ~6),
// so exp() cannot overflow and the result is mathematically identical.
__global__ void __launch_bounds__(512)
softmax_kernel(float* __restrict__ out) {
    const int row = blockIdx.x;
    float4* p4 = (float4*)(out + (size_t)row * MM);
    const int t = threadIdx.x;
    const int lane = t & 31, wd = t >> 5;

    __shared__ float sdata[16];
    __shared__ float sres;

    float4 v[8];
    float lsum = 0.0f;
    #pragma unroll
    for (int i = 0; i < 8; i++) {
        float4 x = p4[t + 512 * i];
        x.x = __expf(x.x); x.y = __expf(x.y);
        x.z = __expf(x.z); x.w = __expf(x.w);
        v[i] = x;
        lsum += (x.x + x.y) + (x.z + x.w);
    }
    #pragma unroll
    for (int o = 16; o; o >>= 1) lsum += __shfl_xor_sync(0xffffffffu, lsum, o);
    if (lane == 0) sdata[wd] = lsum;
    __syncthreads();
    if (wd == 0) {
        float x = (lane < 16) ? sdata[lane] : 0.0f;
        #pragma unroll
        for (int o = 8; o; o >>= 1) x += __shfl_xor_sync(0xffffffffu, x, o);
        if (lane == 0) sres = __fdividef(1.0f, x);
    }
    __syncthreads();
    const float inv = sres;

    #pragma unroll
    for (int i = 0; i < 8; i++) {
        float4 x = v[i];
        x.x *= inv; x.y *= inv; x.z *= inv; x.w *= inv;
        p4[t + 512 * i] = x;
    }
}

extern "C" void kernel_launch(void* const* d_in, const int* in_sizes, int n_in,
                              void* d_out, int out_size) {
    const float* memory    = (const float*)d_in[0];
    const float* keys      = (const float*)d_in[1];
    const float* strengths = (const float*)d_in[2];
    float* out = (float*)d_out;

    cudaFuncSetAttribute(pass1_kernel,
                         cudaFuncAttributeMaxDynamicSharedMemorySize, SM_TOTAL);

    dim3 grid1(MM / MT, BB);
    pass1_kernel<<<grid1, THREADS, SM_TOTAL>>>(memory, keys, strengths, out);
    softmax_kernel<<<BB * HH, 512>>>(out);
}

// round 9
// speedup vs baseline: 1.0265x; 1.0265x over previous
#include <cuda_runtime.h>
#include <math.h>
#include <stdint.h>

#define BB   32
#define MM   16384
#define WW   256
#define HH   16
#define EPS  1e-5f

#define MT      256
#define THREADS 256
#define NCHK    16            // 16-col k chunks
#define DEPTH   4             // cp.async stages per warp

// smem byte layout
#define SM_A     0            // 8 warps x 4 stages x 2048B = 65536
#define SM_BH    65536        // 16 chunks x 4 tiles x 128B = 8192
#define SM_BL    73728        // 8192
#define SM_KN    81920        // 16 f32
#define SM_SP    81984        // 16 f32
#define SM_TOTAL 82048
// sharp staging overlays SM_A after the main loop (16 x 264 f32 = 16896B)
#define SHARP_PITCH 264

__device__ __forceinline__ unsigned pack2(float hi_el, float lo_el) {
    unsigned r;
    asm("cvt.rn.satfinite.bf16x2.f32 %0, %1, %2;" : "=r"(r) : "f"(hi_el), "f"(lo_el));
    return r;
}
__device__ __forceinline__ void ldsm4(unsigned addr, unsigned& r0, unsigned& r1,
                                      unsigned& r2, unsigned& r3) {
    asm volatile("ldmatrix.sync.aligned.m8n8.x4.shared.b16 {%0,%1,%2,%3}, [%4];"
                 : "=r"(r0), "=r"(r1), "=r"(r2), "=r"(r3) : "r"(addr));
}
__device__ __forceinline__ void mma16816(float* d, unsigned a0, unsigned a1,
                                         unsigned a2, unsigned a3,
                                         unsigned b0, unsigned b1) {
    asm volatile(
        "mma.sync.aligned.m16n8k16.row.col.f32.bf16.bf16.f32 "
        "{%0,%1,%2,%3}, {%4,%5,%6,%7}, {%8,%9}, {%0,%1,%2,%3};"
        : "+f"(d[0]), "+f"(d[1]), "+f"(d[2]), "+f"(d[3])
        : "r"(a0), "r"(a1), "r"(a2), "r"(a3), "r"(b0), "r"(b1));
}
__device__ __forceinline__ void cp_async16(unsigned smem_addr, const void* gptr) {
    asm volatile("cp.async.cg.shared.global [%0], [%1], 16;"
                 :: "r"(smem_addr), "l"(gptr));
}
__device__ __forceinline__ void cp_commit() {
    asm volatile("cp.async.commit_group;");
}
__device__ __forceinline__ void cp_wait3() {
    asm volatile("cp.async.wait_group 3;");
}
__device__ __forceinline__ float4 lds128(unsigned addr) {
    float4 v;
    asm volatile("ld.shared.v4.f32 {%0,%1,%2,%3}, [%4];"
                 : "=f"(v.x), "=f"(v.y), "=f"(v.z), "=f"(v.w) : "r"(addr));
    return v;
}
__device__ __forceinline__ float softplus_f(float x) {
    return fmaxf(x, 0.0f) + log1pf(__expf(-fabsf(x)));
}
// split float4 into hi/lo bf16x2 pairs: p01=(x,y), p23=(z,w)
__device__ __forceinline__ void split4(float4 v, unsigned& h01, unsigned& h23,
                                       unsigned& l01, unsigned& l23) {
    h01 = pack2(v.y, v.x);
    h23 = pack2(v.w, v.z);
    float ax = __uint_as_float(h01 << 16);
    float ay = __uint_as_float(h01 & 0xffff0000u);
    float az = __uint_as_float(h23 << 16);
    float aw = __uint_as_float(h23 & 0xffff0000u);
    l01 = pack2(v.y - ay, v.x - ax);
    l23 = pack2(v.w - aw, v.z - az);
}

__global__ void __launch_bounds__(THREADS, 2)
pass1_kernel(const float* __restrict__ memory,
             const float* __restrict__ keys,
             const float* __restrict__ strengths,
             float* __restrict__ out) {
    extern __shared__ char sm[];
    float* smf = (float*)sm;
    unsigned sb;
    asm("{ .reg .u64 t; cvta.to.shared.u64 t, %1; cvt.u32.u64 %0, t; }"
        : "=r"(sb) : "l"(sm));

    const int tid  = threadIdx.x;
    const int lane = tid & 31;
    const int wid  = tid >> 5;
    const int b    = blockIdx.y;
    const int m0   = blockIdx.x * MT;

    const int r = lane >> 2;          // fragment row 0..7
    const int c = lane & 3;           // fragment col group

    // A source: rows (wid*32 + r) + {0,8,16,24}, cols chunk*16 + 4c
    const float* ap = memory + ((size_t)b * MM + m0 + wid * 32 + r) * WW + 4 * c;
    // per-warp smem ring; each lane copies/reads its own 16B
    const unsigned aring = sb + SM_A + wid * (DEPTH * 2048) + lane * 16;

    // ---- prologue: issue stages 0..2 ----
    #pragma unroll
    for (int s = 0; s < DEPTH - 1; s++) {
        #pragma unroll
        for (int j = 0; j < 4; j++)
            cp_async16(aring + s * 2048 + j * 512, ap + (size_t)j * 8 * WW + s * 16);
        cp_commit();
    }

    // ---- keys: permuted bf16 hi/lo B tiles + norms + softplus ----
    {
        const int h = tid >> 4;       // 0..15
        const int t = tid & 15;       // chunk
        const float* kp = keys + (size_t)b * HH * WW + h * WW + t * 16;
        float4 kv[4];
        #pragma unroll
        for (int j = 0; j < 4; j++) kv[j] = *(const float4*)(kp + 4 * j);

        float ss = 0.0f;
        #pragma unroll
        for (int j = 0; j < 4; j++) {
            ss = fmaf(kv[j].x, kv[j].x, ss); ss = fmaf(kv[j].y, kv[j].y, ss);
            ss = fmaf(kv[j].z, kv[j].z, ss); ss = fmaf(kv[j].w, kv[j].w, ss);
        }
        ss += __shfl_xor_sync(0xffffffffu, ss, 1);
        ss += __shfl_xor_sync(0xffffffffu, ss, 2);
        ss += __shfl_xor_sync(0xffffffffu, ss, 4);
        ss += __shfl_xor_sync(0xffffffffu, ss, 8);
        if (t == 0) {
            smf[SM_KN / 4 + h] = sqrtf(ss + EPS);
            smf[SM_SP / 4 + h] = softplus_f(strengths[b * HH + h]);
        }

        // tiles per chunk: [0]=(h0-7,k0-7) [1]=(h8-15,k0-7) [2]=(h0-7,k8-15) [3]=(h8-15,k8-15)
        unsigned base = (unsigned)(t * 512 + (h >> 3) * 128 + (h & 7) * 16);
        #pragma unroll
        for (int q = 0; q < 4; q++) {   // actual col quad
            unsigned h01, h23, l01, l23;
            split4(kv[q], h01, h23, l01, l23);
            *(unsigned*)(sm + SM_BH + base + q * 4)       = h01;
            *(unsigned*)(sm + SM_BH + base + 256 + q * 4) = h23;
            *(unsigned*)(sm + SM_BL + base + q * 4)       = l01;
            *(unsigned*)(sm + SM_BL + base + 256 + q * 4) = l23;
        }
    }
    __syncthreads();

    // ---- main loop: per-warp cp.async pipeline, no barriers ----
    float d[2][2][4];
    #pragma unroll
    for (int mt = 0; mt < 2; mt++)
        #pragma unroll
        for (int nt = 0; nt < 2; nt++)
            #pragma unroll
            for (int i = 0; i < 4; i++) d[mt][nt][i] = 0.0f;

    float ss4[4] = {0.0f, 0.0f, 0.0f, 0.0f};

    const unsigned bl_off = (unsigned)((lane >> 3) * 128 + (lane & 7) * 16);

    for (int t = 0; t < NCHK; t++) {
        // issue chunk t+3 (or empty commit to keep group count uniform)
        if (t + DEPTH - 1 < NCHK) {
            unsigned dst = aring + ((t + DEPTH - 1) & (DEPTH - 1)) * 2048;
            #pragma unroll
            for (int j = 0; j < 4; j++)
                cp_async16(dst + j * 512,
                           ap + (size_t)j * 8 * WW + (t + DEPTH - 1) * 16);
        }
        cp_commit();
        cp_wait3();            // chunk t's group complete

        // B fragments
        unsigned bh[4], bl[4];
        ldsm4(sb + SM_BH + bl_off + t * 512, bh[0], bh[1], bh[2], bh[3]);
        ldsm4(sb + SM_BL + bl_off + t * 512, bl[0], bl[1], bl[2], bl[3]);

        // A from own ring slot + convert + norms
        const unsigned src = aring + (t & (DEPTH - 1)) * 2048;
        unsigned ah01[4], ah23[4], al01[4], al23[4];
        #pragma unroll
        for (int j = 0; j < 4; j++) {
            float4 w = lds128(src + j * 512);
            ss4[j] = fmaf(w.x, w.x, ss4[j]);
            ss4[j] = fmaf(w.y, w.y, ss4[j]);
            ss4[j] = fmaf(w.z, w.z, ss4[j]);
            ss4[j] = fmaf(w.w, w.w, ss4[j]);
            split4(w, ah01[j], ah23[j], al01[j], al23[j]);
        }

        // tile0 = rows (v0, v1), tile1 = rows (v2, v3)
        #pragma unroll
        for (int mt = 0; mt < 2; mt++) {
            int j0 = mt * 2, j1 = mt * 2 + 1;
            mma16816(d[mt][0], ah01[j0], ah01[j1], ah23[j0], ah23[j1], bh[0], bh[2]);
            mma16816(d[mt][0], ah01[j0], ah01[j1], ah23[j0], ah23[j1], bl[0], bl[2]);
            mma16816(d[mt][0], al01[j0], al01[j1], al23[j0], al23[j1], bh[0], bh[2]);
            mma16816(d[mt][1], ah01[j0], ah01[j1], ah23[j0], ah23[j1], bh[1], bh[3]);
            mma16816(d[mt][1], ah01[j0], ah01[j1], ah23[j0], ah23[j1], bl[1], bl[3]);
            mma16816(d[mt][1], al01[j0], al01[j1], al23[j0], al23[j1], bh[1], bh[3]);
        }
    }

    // ---- row norms: reduce across the 4-lane col group ----
    #pragma unroll
    for (int j = 0; j < 4; j++) {
        ss4[j] += __shfl_xor_sync(0xffffffffu, ss4[j], 1);
        ss4[j] += __shfl_xor_sync(0xffffffffu, ss4[j], 2);
        ss4[j] = sqrtf(ss4[j] + EPS);    // mem norm of row (wid*32 + 16*(j>>1) + r + 8*(j&1))
    }

    __syncthreads();   // all warps done with A ring before sharp overlays it

    // ---- sharpen into smem staging (overlays A ring) ----
    {
        float* sharp = smf;   // [16][SHARP_PITCH]
        #pragma unroll
        for (int nt = 0; nt < 2; nt++) {
            int h0 = nt * 8 + 2 * c;
            float sp0 = smf[SM_SP / 4 + h0],     kn0 = smf[SM_KN / 4 + h0];
            float sp1 = smf[SM_SP / 4 + h0 + 1], kn1 = smf[SM_KN / 4 + h0 + 1];
            #pragma unroll
            for (int mt = 0; mt < 2; mt++) {
                int row_lo = wid * 32 + 16 * mt + r;
                float mn_lo = ss4[2 * mt];
                float mn_hi = ss4[2 * mt + 1];
                sharp[h0 * SHARP_PITCH + row_lo] =
                    __fdividef(d[mt][nt][0] * sp0, fmaf(kn0, mn_lo, EPS));
                sharp[(h0 + 1) * SHARP_PITCH + row_lo] =
                    __fdividef(d[mt][nt][1] * sp1, fmaf(kn1, mn_lo, EPS));
                sharp[h0 * SHARP_PITCH + row_lo + 8] =
                    __fdividef(d[mt][nt][2] * sp0, fmaf(kn0, mn_hi, EPS));
                sharp[(h0 + 1) * SHARP_PITCH + row_lo + 8] =
                    __fdividef(d[mt][nt][3] * sp1, fmaf(kn1, mn_hi, EPS));
            }
        }
    }
    __syncthreads();

    // ---- coalesced write ----
    {
        const float* sharp = smf;
        float4* o4 = (float4*)out;
        #pragma unroll
        for (int u = 0; u < 4; u++) {
            int f  = tid + 256 * u;     // 1024 float4
            int h  = f >> 6;
            int r4 = f & 63;
            float4 w = *(const float4*)(sharp + h * SHARP_PITCH + r4 * 4);
            o4[(((size_t)b * HH + h) * MM + m0) / 4 + r4] = w;
        }
    }
}

// ---- pass 2: in-place softmax over M per (b,h) row ----
// No max-subtraction: sharp = cos_sim * softplus(strength) is bounded (|x| < ~6),
// so exp() cannot overflow and the result is mathematically identical.
__global__ void __launch_bounds__(512)
softmax_kernel(float* __restrict__ out) {
    const int row = blockIdx.x;
    float4* p4 = (float4*)(out + (size_t)row * MM);
    const int t = threadIdx.x;
    const int lane = t & 31, wd = t >> 5;

    __shared__ float sdata[16];
    __shared__ float sres;

    float4 v[8];
    float lsum = 0.0f;
    #pragma unroll
    for (int i = 0; i < 8; i++) {
        float4 x = p4[t + 512 * i];
        x.x = __expf(x.x); x.y = __expf(x.y);
        x.z = __expf(x.z); x.w = __expf(x.w);
        v[i] = x;
        lsum += (x.x + x.y) + (x.z + x.w);
    }
    #pragma unroll
    for (int o = 16; o; o >>= 1) lsum += __shfl_xor_sync(0xffffffffu, lsum, o);
    if (lane == 0) sdata[wd] = lsum;
    __syncthreads();
    if (wd == 0) {
        float x = (lane < 16) ? sdata[lane] : 0.0f;
        #pragma unroll
        for (int o = 8; o; o >>= 1) x += __shfl_xor_sync(0xffffffffu, x, o);
        if (lane == 0) sres = __fdividef(1.0f, x);
    }
    __syncthreads();
    const float inv = sres;

    #pragma unroll
    for (int i = 0; i < 8; i++) {
        float4 x = v[i];
        x.x *= inv; x.y *= inv; x.z *= inv; x.w *= inv;
        __stcs(p4 + t + 512 * i, x);   // streaming store: output never re-read
    }
}

extern "C" void kernel_launch(void* const* d_in, const int* in_sizes, int n_in,
                              void* d_out, int out_size) {
    const float* memory    = (const float*)d_in[0];
    const float* keys      = (const float*)d_in[1];
    const float* strengths = (const float*)d_in[2];
    float* out = (float*)d_out;

    cudaFuncSetAttribute(pass1_kernel,
                         cudaFuncAttributeMaxDynamicSharedMemorySize, SM_TOTAL);

    dim3 grid1(MM / MT, BB);
    pass1_kernel<<<grid1, THREADS, SM_TOTAL>>>(memory, keys, strengths, out);
    softmax_kernel<<<BB * HH, 512>>>(out);
}

// round 10
// speedup vs baseline: 1.0664x; 1.0389x over previous
#include <cuda_runtime.h>
#include <math.h>
#include <stdint.h>

#define BB   32
#define MM   16384
#define WW   256
#define HH   16
#define EPS  1e-5f

#define MT      256
#define THREADS 256
#define NCHK    16            // 16-col k chunks
#define DEPTH   4             // cp.async stages per warp

// smem byte layout
#define SM_A     0            // 8 warps x 4 stages x 2048B = 65536
#define SM_BH    65536        // 16 chunks x 4 tiles x 128B = 8192
#define SM_BL    73728        // 8192
#define SM_KN    81920        // 16 f32
#define SM_SP    81984        // 16 f32
#define SM_TOTAL 82048

__device__ __forceinline__ unsigned pack2(float hi_el, float lo_el) {
    unsigned r;
    asm("cvt.rn.satfinite.bf16x2.f32 %0, %1, %2;" : "=r"(r) : "f"(hi_el), "f"(lo_el));
    return r;
}
__device__ __forceinline__ void ldsm4(unsigned addr, unsigned& r0, unsigned& r1,
                                      unsigned& r2, unsigned& r3) {
    asm volatile("ldmatrix.sync.aligned.m8n8.x4.shared.b16 {%0,%1,%2,%3}, [%4];"
                 : "=r"(r0), "=r"(r1), "=r"(r2), "=r"(r3) : "r"(addr));
}
__device__ __forceinline__ void mma16816(float* d, unsigned a0, unsigned a1,
                                         unsigned a2, unsigned a3,
                                         unsigned b0, unsigned b1) {
    asm volatile(
        "mma.sync.aligned.m16n8k16.row.col.f32.bf16.bf16.f32 "
        "{%0,%1,%2,%3}, {%4,%5,%6,%7}, {%8,%9}, {%0,%1,%2,%3};"
        : "+f"(d[0]), "+f"(d[1]), "+f"(d[2]), "+f"(d[3])
        : "r"(a0), "r"(a1), "r"(a2), "r"(a3), "r"(b0), "r"(b1));
}
__device__ __forceinline__ void cp_async16(unsigned smem_addr, const void* gptr) {
    asm volatile("cp.async.cg.shared.global [%0], [%1], 16;"
                 :: "r"(smem_addr), "l"(gptr));
}
__device__ __forceinline__ void cp_commit() {
    asm volatile("cp.async.commit_group;");
}
__device__ __forceinline__ void cp_wait3() {
    asm volatile("cp.async.wait_group 3;");
}
__device__ __forceinline__ float4 lds128(unsigned addr) {
    float4 v;
    asm volatile("ld.shared.v4.f32 {%0,%1,%2,%3}, [%4];"
                 : "=f"(v.x), "=f"(v.y), "=f"(v.z), "=f"(v.w) : "r"(addr));
    return v;
}
__device__ __forceinline__ float softplus_f(float x) {
    return fmaxf(x, 0.0f) + log1pf(__expf(-fabsf(x)));
}
// split float4 into hi/lo bf16x2 pairs: p01=(x,y), p23=(z,w)
__device__ __forceinline__ void split4(float4 v, unsigned& h01, unsigned& h23,
                                       unsigned& l01, unsigned& l23) {
    h01 = pack2(v.y, v.x);
    h23 = pack2(v.w, v.z);
    float ax = __uint_as_float(h01 << 16);
    float ay = __uint_as_float(h01 & 0xffff0000u);
    float az = __uint_as_float(h23 << 16);
    float aw = __uint_as_float(h23 & 0xffff0000u);
    l01 = pack2(v.y - ay, v.x - ax);
    l23 = pack2(v.w - aw, v.z - az);
}

__global__ void __launch_bounds__(THREADS, 2)
pass1_kernel(const float* __restrict__ memory,
             const float* __restrict__ keys,
             const float* __restrict__ strengths,
             float* __restrict__ out) {
    extern __shared__ char sm[];
    float* smf = (float*)sm;
    unsigned sb;
    asm("{ .reg .u64 t; cvta.to.shared.u64 t, %1; cvt.u32.u64 %0, t; }"
        : "=r"(sb) : "l"(sm));

    const int tid  = threadIdx.x;
    const int lane = tid & 31;
    const int wid  = tid >> 5;
    const int b    = blockIdx.y;
    const int m0   = blockIdx.x * MT;

    const int r = lane >> 2;          // fragment row 0..7
    const int c = lane & 3;           // fragment col group

    // A source: rows (wid*32 + r) + {0,8,16,24}, cols chunk*16 + 4c
    const float* ap = memory + ((size_t)b * MM + m0 + wid * 32 + r) * WW + 4 * c;
    // per-warp smem ring; each lane copies/reads its own 16B
    const unsigned aring = sb + SM_A + wid * (DEPTH * 2048) + lane * 16;

    // ---- prologue: issue stages 0..2 ----
    #pragma unroll
    for (int s = 0; s < DEPTH - 1; s++) {
        #pragma unroll
        for (int j = 0; j < 4; j++)
            cp_async16(aring + s * 2048 + j * 512, ap + (size_t)j * 8 * WW + s * 16);
        cp_commit();
    }

    // ---- keys: permuted bf16 hi/lo B tiles + norms + softplus ----
    {
        const int h = tid >> 4;       // 0..15
        const int t = tid & 15;       // chunk
        const float* kp = keys + (size_t)b * HH * WW + h * WW + t * 16;
        float4 kv[4];
        #pragma unroll
        for (int j = 0; j < 4; j++) kv[j] = *(const float4*)(kp + 4 * j);

        float ss = 0.0f;
        #pragma unroll
        for (int j = 0; j < 4; j++) {
            ss = fmaf(kv[j].x, kv[j].x, ss); ss = fmaf(kv[j].y, kv[j].y, ss);
            ss = fmaf(kv[j].z, kv[j].z, ss); ss = fmaf(kv[j].w, kv[j].w, ss);
        }
        ss += __shfl_xor_sync(0xffffffffu, ss, 1);
        ss += __shfl_xor_sync(0xffffffffu, ss, 2);
        ss += __shfl_xor_sync(0xffffffffu, ss, 4);
        ss += __shfl_xor_sync(0xffffffffu, ss, 8);
        if (t == 0) {
            smf[SM_KN / 4 + h] = sqrtf(ss + EPS);
            smf[SM_SP / 4 + h] = softplus_f(strengths[b * HH + h]);
        }

        // tiles per chunk: [0]=(h0-7,k0-7) [1]=(h8-15,k0-7) [2]=(h0-7,k8-15) [3]=(h8-15,k8-15)
        unsigned base = (unsigned)(t * 512 + (h >> 3) * 128 + (h & 7) * 16);
        #pragma unroll
        for (int q = 0; q < 4; q++) {   // actual col quad
            unsigned h01, h23, l01, l23;
            split4(kv[q], h01, h23, l01, l23);
            *(unsigned*)(sm + SM_BH + base + q * 4)       = h01;
            *(unsigned*)(sm + SM_BH + base + 256 + q * 4) = h23;
            *(unsigned*)(sm + SM_BL + base + q * 4)       = l01;
            *(unsigned*)(sm + SM_BL + base + 256 + q * 4) = l23;
        }
    }
    __syncthreads();

    // ---- main loop: per-warp cp.async pipeline, no barriers ----
    float d[2][2][4];
    #pragma unroll
    for (int mt = 0; mt < 2; mt++)
        #pragma unroll
        for (int nt = 0; nt < 2; nt++)
            #pragma unroll
            for (int i = 0; i < 4; i++) d[mt][nt][i] = 0.0f;

    float ss4[4] = {0.0f, 0.0f, 0.0f, 0.0f};

    const unsigned bl_off = (unsigned)((lane >> 3) * 128 + (lane & 7) * 16);

    for (int t = 0; t < NCHK; t++) {
        // issue chunk t+3 (or empty commit to keep group count uniform)
        if (t + DEPTH - 1 < NCHK) {
            unsigned dst = aring + ((t + DEPTH - 1) & (DEPTH - 1)) * 2048;
            #pragma unroll
            for (int j = 0; j < 4; j++)
                cp_async16(dst + j * 512,
                           ap + (size_t)j * 8 * WW + (t + DEPTH - 1) * 16);
        }
        cp_commit();
        cp_wait3();            // chunk t's group complete

        // B fragments
        unsigned bh[4], bl[4];
        ldsm4(sb + SM_BH + bl_off + t * 512, bh[0], bh[1], bh[2], bh[3]);
        ldsm4(sb + SM_BL + bl_off + t * 512, bl[0], bl[1], bl[2], bl[3]);

        // A from own ring slot + convert + norms
        const unsigned src = aring + (t & (DEPTH - 1)) * 2048;
        unsigned ah01[4], ah23[4], al01[4], al23[4];
        #pragma unroll
        for (int j = 0; j < 4; j++) {
            float4 w = lds128(src + j * 512);
            ss4[j] = fmaf(w.x, w.x, ss4[j]);
            ss4[j] = fmaf(w.y, w.y, ss4[j]);
            ss4[j] = fmaf(w.z, w.z, ss4[j]);
            ss4[j] = fmaf(w.w, w.w, ss4[j]);
            split4(w, ah01[j], ah23[j], al01[j], al23[j]);
        }

        // tile0 = rows (v0, v1), tile1 = rows (v2, v3)
        #pragma unroll
        for (int mt = 0; mt < 2; mt++) {
            int j0 = mt * 2, j1 = mt * 2 + 1;
            mma16816(d[mt][0], ah01[j0], ah01[j1], ah23[j0], ah23[j1], bh[0], bh[2]);
            mma16816(d[mt][0], ah01[j0], ah01[j1], ah23[j0], ah23[j1], bl[0], bl[2]);
            mma16816(d[mt][0], al01[j0], al01[j1], al23[j0], al23[j1], bh[0], bh[2]);
            mma16816(d[mt][1], ah01[j0], ah01[j1], ah23[j0], ah23[j1], bh[1], bh[3]);
            mma16816(d[mt][1], ah01[j0], ah01[j1], ah23[j0], ah23[j1], bl[1], bl[3]);
            mma16816(d[mt][1], al01[j0], al01[j1], al23[j0], al23[j1], bh[1], bh[3]);
        }
    }

    // ---- row norms: reduce across the 4-lane col group ----
    #pragma unroll
    for (int j = 0; j < 4; j++) {
        ss4[j] += __shfl_xor_sync(0xffffffffu, ss4[j], 1);
        ss4[j] += __shfl_xor_sync(0xffffffffu, ss4[j], 2);
        ss4[j] = sqrtf(ss4[j] + EPS);    // mem norm of row (wid*32 + 16*(j>>1) + r + 8*(j&1))
    }

    // ---- epilogue: sharpen + direct scalar stores (sector-aligned) ----
    // head h = nt*8 + 2c + (i&1), row = wid*32 + 16mt + r + 8*(i>>1).
    // For fixed h, lanes r=0..7 write 8 consecutive floats = 1 full 32B sector.
    {
        const size_t ob = (size_t)b * HH * MM + m0 + wid * 32 + r;
        #pragma unroll
        for (int nt = 0; nt < 2; nt++) {
            int h0 = nt * 8 + 2 * c;
            float sp0 = smf[SM_SP / 4 + h0],     kn0 = smf[SM_KN / 4 + h0];
            float sp1 = smf[SM_SP / 4 + h0 + 1], kn1 = smf[SM_KN / 4 + h0 + 1];
            #pragma unroll
            for (int mt = 0; mt < 2; mt++) {
                float mn_lo = ss4[2 * mt];
                float mn_hi = ss4[2 * mt + 1];
                float* p0 = out + ob + (size_t)h0 * MM + 16 * mt;
                float* p1 = p0 + MM;
                p0[0] = __fdividef(d[mt][nt][0] * sp0, fmaf(kn0, mn_lo, EPS));
                p1[0] = __fdividef(d[mt][nt][1] * sp1, fmaf(kn1, mn_lo, EPS));
                p0[8] = __fdividef(d[mt][nt][2] * sp0, fmaf(kn0, mn_hi, EPS));
                p1[8] = __fdividef(d[mt][nt][3] * sp1, fmaf(kn1, mn_hi, EPS));
            }
        }
    }
}

// ---- pass 2: in-place softmax over M per (b,h) row ----
// No max-subtraction: sharp = cos_sim * softplus(strength) is bounded (|x| < ~6),
// so exp() cannot overflow and the result is mathematically identical.
__global__ void __launch_bounds__(512)
softmax_kernel(float* __restrict__ out) {
    const int row = blockIdx.x;
    float4* p4 = (float4*)(out + (size_t)row * MM);
    const int t = threadIdx.x;
    const int lane = t & 31, wd = t >> 5;

    __shared__ float sdata[16];
    __shared__ float sres;

    float4 v[8];
    float lsum = 0.0f;
    #pragma unroll
    for (int i = 0; i < 8; i++) {
        float4 x = p4[t + 512 * i];
        x.x = __expf(x.x); x.y = __expf(x.y);
        x.z = __expf(x.z); x.w = __expf(x.w);
        v[i] = x;
        lsum += (x.x + x.y) + (x.z + x.w);
    }
    #pragma unroll
    for (int o = 16; o; o >>= 1) lsum += __shfl_xor_sync(0xffffffffu, lsum, o);
    if (lane == 0) sdata[wd] = lsum;
    __syncthreads();
    if (wd == 0) {
        float x = (lane < 16) ? sdata[lane] : 0.0f;
        #pragma unroll
        for (int o = 8; o; o >>= 1) x += __shfl_xor_sync(0xffffffffu, x, o);
        if (lane == 0) sres = __fdividef(1.0f, x);
    }
    __syncthreads();
    const float inv = sres;

    #pragma unroll
    for (int i = 0; i < 8; i++) {
        float4 x = v[i];
        x.x *= inv; x.y *= inv; x.z *= inv; x.w *= inv;
        __stcs(p4 + t + 512 * i, x);   // streaming store: output never re-read
    }
}

extern "C" void kernel_launch(void* const* d_in, const int* in_sizes, int n_in,
                              void* d_out, int out_size) {
    const float* memory    = (const float*)d_in[0];
    const float* keys      = (const float*)d_in[1];
    const float* strengths = (const float*)d_in[2];
    float* out = (float*)d_out;

    cudaFuncSetAttribute(pass1_kernel,
                         cudaFuncAttributeMaxDynamicSharedMemorySize, SM_TOTAL);

    dim3 grid1(MM / MT, BB);
    pass1_kernel<<<grid1, THREADS, SM_TOTAL>>>(memory, keys, strengths, out);
    softmax_kernel<<<BB * HH, 512>>>(out);
}